// round 1
// baseline (speedup 1.0000x reference)
#include <cuda_runtime.h>
#include <math.h>

// ---------------------------------------------------------------------------
// Problem: out[i,j,k] = trilinear(vol, T @ [i,j,k,1]) with zero outside bounds
// T = inv(flo_v2r) @ (Tci @ Tt @ Tr @ Tc) @ ref_v2r   (rows 0..2 used)
// Shapes: vol 256x256x256 f32, out same.
// ---------------------------------------------------------------------------

#define D_DIM 256
#define H_DIM 256
#define W_DIM 256

__device__ float g_T[12];  // 3x4 row-major transform

// ---- 4x4 helpers (device, single thread) ----
__device__ __forceinline__ void mat4_mul(const float* A, const float* B, float* C) {
    for (int r = 0; r < 4; ++r)
        for (int c = 0; c < 4; ++c) {
            float s = 0.f;
            for (int m = 0; m < 4; ++m) s += A[r * 4 + m] * B[m * 4 + c];
            C[r * 4 + c] = s;
        }
}

// General 4x4 inverse via cofactors (adjugate). Matrices here are near-identity
// affines, so conditioning is excellent.
__device__ void mat4_inv(const float* m, float* inv) {
    inv[0]  =  m[5]*m[10]*m[15] - m[5]*m[11]*m[14] - m[9]*m[6]*m[15] + m[9]*m[7]*m[14] + m[13]*m[6]*m[11] - m[13]*m[7]*m[10];
    inv[4]  = -m[4]*m[10]*m[15] + m[4]*m[11]*m[14] + m[8]*m[6]*m[15] - m[8]*m[7]*m[14] - m[12]*m[6]*m[11] + m[12]*m[7]*m[10];
    inv[8]  =  m[4]*m[9]*m[15]  - m[4]*m[11]*m[13] - m[8]*m[5]*m[15] + m[8]*m[7]*m[13] + m[12]*m[5]*m[11] - m[12]*m[7]*m[9];
    inv[12] = -m[4]*m[9]*m[14]  + m[4]*m[10]*m[13] + m[8]*m[5]*m[14] - m[8]*m[6]*m[13] - m[12]*m[5]*m[10] + m[12]*m[6]*m[9];
    inv[1]  = -m[1]*m[10]*m[15] + m[1]*m[11]*m[14] + m[9]*m[2]*m[15] - m[9]*m[3]*m[14] - m[13]*m[2]*m[11] + m[13]*m[3]*m[10];
    inv[5]  =  m[0]*m[10]*m[15] - m[0]*m[11]*m[14] - m[8]*m[2]*m[15] + m[8]*m[3]*m[14] + m[12]*m[2]*m[11] - m[12]*m[3]*m[10];
    inv[9]  = -m[0]*m[9]*m[15]  + m[0]*m[11]*m[13] + m[8]*m[1]*m[15] - m[8]*m[3]*m[13] - m[12]*m[1]*m[11] + m[12]*m[3]*m[9];
    inv[13] =  m[0]*m[9]*m[14]  - m[0]*m[10]*m[13] - m[8]*m[1]*m[14] + m[8]*m[2]*m[13] + m[12]*m[1]*m[10] - m[12]*m[2]*m[9];
    inv[2]  =  m[1]*m[6]*m[15]  - m[1]*m[7]*m[14]  - m[5]*m[2]*m[15] + m[5]*m[3]*m[14] + m[13]*m[2]*m[7]  - m[13]*m[3]*m[6];
    inv[6]  = -m[0]*m[6]*m[15]  + m[0]*m[7]*m[14]  + m[4]*m[2]*m[15] - m[4]*m[3]*m[14] - m[12]*m[2]*m[7]  + m[12]*m[3]*m[6];
    inv[10] =  m[0]*m[5]*m[15]  - m[0]*m[7]*m[13]  - m[4]*m[1]*m[15] + m[4]*m[3]*m[13] + m[12]*m[1]*m[7]  - m[12]*m[3]*m[5];
    inv[14] = -m[0]*m[5]*m[14]  + m[0]*m[6]*m[13]  + m[4]*m[1]*m[14] - m[4]*m[2]*m[13] - m[12]*m[1]*m[6]  + m[12]*m[2]*m[5];
    inv[3]  = -m[1]*m[6]*m[11]  + m[1]*m[7]*m[10]  + m[5]*m[2]*m[11] - m[5]*m[3]*m[10] - m[9]*m[2]*m[7]   + m[9]*m[3]*m[6];
    inv[7]  =  m[0]*m[6]*m[11]  - m[0]*m[7]*m[10]  - m[4]*m[2]*m[11] + m[4]*m[3]*m[10] + m[8]*m[2]*m[7]   - m[8]*m[3]*m[6];
    inv[11] = -m[0]*m[5]*m[11]  + m[0]*m[7]*m[9]   + m[4]*m[1]*m[11] - m[4]*m[3]*m[9]  - m[8]*m[1]*m[7]   + m[8]*m[3]*m[5];
    inv[15] =  m[0]*m[5]*m[10]  - m[0]*m[6]*m[9]   - m[4]*m[1]*m[10] + m[4]*m[2]*m[9]  + m[8]*m[1]*m[6]   - m[8]*m[2]*m[5];
    float det = m[0]*inv[0] + m[1]*inv[4] + m[2]*inv[8] + m[3]*inv[12];
    float id = 1.0f / det;
    for (int i = 0; i < 16; ++i) inv[i] *= id;
}

__global__ void compute_T_kernel(const float* __restrict__ angle,
                                 const float* __restrict__ trans,
                                 const float* __restrict__ ref_v2r,
                                 const float* __restrict__ flo_v2r,
                                 const float* __restrict__ cog) {
    if (threadIdx.x != 0 || blockIdx.x != 0) return;

    float ax = angle[0], ay = angle[1], az = angle[2];
    float cx = cosf(ax), sx = sinf(ax);
    float cy = cosf(ay), sy = sinf(ay);
    float cz = cosf(az), sz = sinf(az);

    // R = Rx @ Ry @ Rz
    float Rx[9] = {1, 0, 0, 0, cx, -sx, 0, sx, cx};
    float Ry[9] = {cy, 0, sy, 0, 1, 0, -sy, 0, cy};
    float Rz[9] = {cz, -sz, 0, sz, cz, 0, 0, 0, 1};
    float Rxy[9], R[9];
    for (int r = 0; r < 3; ++r)
        for (int c = 0; c < 3; ++c) {
            float s = 0.f;
            for (int m = 0; m < 3; ++m) s += Rx[r*3+m] * Ry[m*3+c];
            Rxy[r*3+c] = s;
        }
    for (int r = 0; r < 3; ++r)
        for (int c = 0; c < 3; ++c) {
            float s = 0.f;
            for (int m = 0; m < 3; ++m) s += Rxy[r*3+m] * Rz[m*3+c];
            R[r*3+c] = s;
        }

    // Build 4x4s: Tc (translate -cog), Tci (+cog), Tt (translate t), Tr (rotation)
    float Tc[16]  = {1,0,0,-cog[0], 0,1,0,-cog[1], 0,0,1,-cog[2], 0,0,0,1};
    float Tci[16] = {1,0,0, cog[0], 0,1,0, cog[1], 0,0,1, cog[2], 0,0,0,1};
    float Tt[16]  = {1,0,0,trans[0], 0,1,0,trans[1], 0,0,1,trans[2], 0,0,0,1};
    float Tr[16]  = {R[0],R[1],R[2],0, R[3],R[4],R[5],0, R[6],R[7],R[8],0, 0,0,0,1};

    float tmp1[16], tmp2[16], Trig[16];
    mat4_mul(Tr, Tc, tmp1);        // Tr @ Tc
    mat4_mul(Tt, tmp1, tmp2);      // Tt @ Tr @ Tc
    mat4_mul(Tci, tmp2, Trig);     // Tci @ Tt @ Tr @ Tc

    float flo_inv[16];
    mat4_inv(flo_v2r, flo_inv);

    float tmp3[16], T[16];
    mat4_mul(Trig, ref_v2r, tmp3); // Trig @ ref
    mat4_mul(flo_inv, tmp3, T);    // inv(flo) @ Trig @ ref

    for (int r = 0; r < 3; ++r)
        for (int c = 0; c < 4; ++c)
            g_T[r * 4 + c] = T[r * 4 + c];
}

// ---- main resample kernel: one thread per output voxel ----
__global__ void __launch_bounds__(256)
warp_trilinear_kernel(const float* __restrict__ vol, float* __restrict__ out) {
    const int k = threadIdx.x;          // 0..255
    const int j = blockIdx.y;           // 0..255
    const int i = blockIdx.z;           // 0..255

    const float fi_in = (float)i, fj_in = (float)j, fk_in = (float)k;

    const float T00 = g_T[0], T01 = g_T[1], T02 = g_T[2],  T03 = g_T[3];
    const float T10 = g_T[4], T11 = g_T[5], T12 = g_T[6],  T13 = g_T[7];
    const float T20 = g_T[8], T21 = g_T[9], T22 = g_T[10], T23 = g_T[11];

    float di = fmaf(T00, fi_in, fmaf(T01, fj_in, fmaf(T02, fk_in, T03)));
    float dj = fmaf(T10, fi_in, fmaf(T11, fj_in, fmaf(T12, fk_in, T13)));
    float dk = fmaf(T20, fi_in, fmaf(T21, fj_in, fmaf(T22, fk_in, T23)));

    const float DM1 = (float)(D_DIM - 1), HM1 = (float)(H_DIM - 1), WM1 = (float)(W_DIM - 1);
    const bool ok = (di >= 0.f) & (di <= DM1) & (dj >= 0.f) & (dj <= HM1)
                  & (dk >= 0.f) & (dk <= WM1);

    di = fminf(fmaxf(di, 0.f), DM1);
    dj = fminf(fmaxf(dj, 0.f), HM1);
    dk = fminf(fmaxf(dk, 0.f), WM1);

    const int fi = (int)floorf(di);
    const int fj = (int)floorf(dj);
    const int fk = (int)floorf(dk);
    const int ci = min(fi + 1, D_DIM - 1);
    const int cj = min(fj + 1, H_DIM - 1);
    const int ck = min(fk + 1, W_DIM - 1);

    const float wi = di - (float)fi;
    const float wj = dj - (float)fj;
    const float wk = dk - (float)fk;

    const long base_ff = ((long)fi * H_DIM + fj) * W_DIM;
    const long base_fc = ((long)fi * H_DIM + cj) * W_DIM;
    const long base_cf = ((long)ci * H_DIM + fj) * W_DIM;
    const long base_cc = ((long)ci * H_DIM + cj) * W_DIM;

    const float v000 = __ldg(vol + base_ff + fk);
    const float v001 = __ldg(vol + base_ff + ck);
    const float v010 = __ldg(vol + base_fc + fk);
    const float v011 = __ldg(vol + base_fc + ck);
    const float v100 = __ldg(vol + base_cf + fk);
    const float v101 = __ldg(vol + base_cf + ck);
    const float v110 = __ldg(vol + base_cc + fk);
    const float v111 = __ldg(vol + base_cc + ck);

    // lerp along k, then j, then i
    const float c00 = fmaf(wk, v001 - v000, v000);
    const float c01 = fmaf(wk, v011 - v010, v010);
    const float c10 = fmaf(wk, v101 - v100, v100);
    const float c11 = fmaf(wk, v111 - v110, v110);
    const float c0  = fmaf(wj, c01 - c00, c00);
    const float c1  = fmaf(wj, c11 - c10, c10);
    float r        = fmaf(wi, c1 - c0, c0);

    r = ok ? r : 0.f;

    out[((long)i * H_DIM + j) * W_DIM + k] = r;
}

extern "C" void kernel_launch(void* const* d_in, const int* in_sizes, int n_in,
                              void* d_out, int out_size) {
    const float* image = (const float*)d_in[0];   // [1,1,256,256,256]
    const float* angle = (const float*)d_in[1];   // [1,3]
    const float* trans = (const float*)d_in[2];   // [1,3]
    const float* ref_v2r = (const float*)d_in[3]; // [4,4]
    const float* flo_v2r = (const float*)d_in[4]; // [4,4]
    const float* cog = (const float*)d_in[5];     // [3]
    float* out = (float*)d_out;

    compute_T_kernel<<<1, 1>>>(angle, trans, ref_v2r, flo_v2r, cog);

    dim3 block(256, 1, 1);
    dim3 grid(1, H_DIM, D_DIM);
    warp_trilinear_kernel<<<grid, block>>>(image, out);
}

// round 2
// speedup vs baseline: 1.3072x; 1.3072x over previous
#include <cuda_runtime.h>
#include <math.h>

// ---------------------------------------------------------------------------
// out[i,j,k] = trilinear(vol, T @ [i,j,k,1]) with zero outside bounds
// T = inv(flo_v2r) @ (Tci @ Tt @ Tr @ Tc) @ ref_v2r   (rows 0..2 used)
// vol/out: 256^3 f32.
//
// R1 -> R2 change: T coefficients move from __device__ global (12 LDG/thread)
// to __constant__ memory (c-bank operands, 0 LDG/thread). Filled by a
// device-to-symbol async memcpy after the 1-thread setup kernel; fully
// graph-capturable.
// ---------------------------------------------------------------------------

#define D_DIM 256
#define H_DIM 256
#define W_DIM 256

__device__ float g_T[12];      // written by setup kernel
__constant__ float c_T[12];    // read by main kernel (c-bank)

// ---- 4x4 helpers (device, single thread) ----
__device__ __forceinline__ void mat4_mul(const float* A, const float* B, float* C) {
    for (int r = 0; r < 4; ++r)
        for (int c = 0; c < 4; ++c) {
            float s = 0.f;
            for (int m = 0; m < 4; ++m) s += A[r * 4 + m] * B[m * 4 + c];
            C[r * 4 + c] = s;
        }
}

__device__ void mat4_inv(const float* m, float* inv) {
    inv[0]  =  m[5]*m[10]*m[15] - m[5]*m[11]*m[14] - m[9]*m[6]*m[15] + m[9]*m[7]*m[14] + m[13]*m[6]*m[11] - m[13]*m[7]*m[10];
    inv[4]  = -m[4]*m[10]*m[15] + m[4]*m[11]*m[14] + m[8]*m[6]*m[15] - m[8]*m[7]*m[14] - m[12]*m[6]*m[11] + m[12]*m[7]*m[10];
    inv[8]  =  m[4]*m[9]*m[15]  - m[4]*m[11]*m[13] - m[8]*m[5]*m[15] + m[8]*m[7]*m[13] + m[12]*m[5]*m[11] - m[12]*m[7]*m[9];
    inv[12] = -m[4]*m[9]*m[14]  + m[4]*m[10]*m[13] + m[8]*m[5]*m[14] - m[8]*m[6]*m[13] - m[12]*m[5]*m[10] + m[12]*m[6]*m[9];
    inv[1]  = -m[1]*m[10]*m[15] + m[1]*m[11]*m[14] + m[9]*m[2]*m[15] - m[9]*m[3]*m[14] - m[13]*m[2]*m[11] + m[13]*m[3]*m[10];
    inv[5]  =  m[0]*m[10]*m[15] - m[0]*m[11]*m[14] - m[8]*m[2]*m[15] + m[8]*m[3]*m[14] + m[12]*m[2]*m[11] - m[12]*m[3]*m[10];
    inv[9]  = -m[0]*m[9]*m[15]  + m[0]*m[11]*m[13] + m[8]*m[1]*m[15] - m[8]*m[3]*m[13] - m[12]*m[1]*m[11] + m[12]*m[3]*m[9];
    inv[13] =  m[0]*m[9]*m[14]  - m[0]*m[10]*m[13] - m[8]*m[1]*m[14] + m[8]*m[2]*m[13] + m[12]*m[1]*m[10] - m[12]*m[2]*m[9];
    inv[2]  =  m[1]*m[6]*m[15]  - m[1]*m[7]*m[14]  - m[5]*m[2]*m[15] + m[5]*m[3]*m[14] + m[13]*m[2]*m[7]  - m[13]*m[3]*m[6];
    inv[6]  = -m[0]*m[6]*m[15]  + m[0]*m[7]*m[14]  + m[4]*m[2]*m[15] - m[4]*m[3]*m[14] - m[12]*m[2]*m[7]  + m[12]*m[3]*m[6];
    inv[10] =  m[0]*m[5]*m[15]  - m[0]*m[7]*m[13]  - m[4]*m[1]*m[15] + m[4]*m[3]*m[13] + m[12]*m[1]*m[7]  - m[12]*m[3]*m[5];
    inv[14] = -m[0]*m[5]*m[14]  + m[0]*m[6]*m[13]  + m[4]*m[1]*m[14] - m[4]*m[2]*m[13] - m[12]*m[1]*m[6]  + m[12]*m[2]*m[5];
    inv[3]  = -m[1]*m[6]*m[11]  + m[1]*m[7]*m[10]  + m[5]*m[2]*m[11] - m[5]*m[3]*m[10] - m[9]*m[2]*m[7]   + m[9]*m[3]*m[6];
    inv[7]  =  m[0]*m[6]*m[11]  - m[0]*m[7]*m[10]  - m[4]*m[2]*m[11] + m[4]*m[3]*m[10] + m[8]*m[2]*m[7]   - m[8]*m[3]*m[6];
    inv[11] = -m[0]*m[5]*m[11]  + m[0]*m[7]*m[9]   + m[4]*m[1]*m[11] - m[4]*m[3]*m[9]  - m[8]*m[1]*m[7]   + m[8]*m[3]*m[5];
    inv[15] =  m[0]*m[5]*m[10]  - m[0]*m[6]*m[9]   - m[4]*m[1]*m[10] + m[4]*m[2]*m[9]  + m[8]*m[1]*m[6]   - m[8]*m[2]*m[5];
    float det = m[0]*inv[0] + m[1]*inv[4] + m[2]*inv[8] + m[3]*inv[12];
    float id = 1.0f / det;
    for (int i = 0; i < 16; ++i) inv[i] *= id;
}

__global__ void compute_T_kernel(const float* __restrict__ angle,
                                 const float* __restrict__ trans,
                                 const float* __restrict__ ref_v2r,
                                 const float* __restrict__ flo_v2r,
                                 const float* __restrict__ cog) {
    if (threadIdx.x != 0 || blockIdx.x != 0) return;

    float ax = angle[0], ay = angle[1], az = angle[2];
    float cx = cosf(ax), sx = sinf(ax);
    float cy = cosf(ay), sy = sinf(ay);
    float cz = cosf(az), sz = sinf(az);

    float Rx[9] = {1, 0, 0, 0, cx, -sx, 0, sx, cx};
    float Ry[9] = {cy, 0, sy, 0, 1, 0, -sy, 0, cy};
    float Rz[9] = {cz, -sz, 0, sz, cz, 0, 0, 0, 1};
    float Rxy[9], R[9];
    for (int r = 0; r < 3; ++r)
        for (int c = 0; c < 3; ++c) {
            float s = 0.f;
            for (int m = 0; m < 3; ++m) s += Rx[r*3+m] * Ry[m*3+c];
            Rxy[r*3+c] = s;
        }
    for (int r = 0; r < 3; ++r)
        for (int c = 0; c < 3; ++c) {
            float s = 0.f;
            for (int m = 0; m < 3; ++m) s += Rxy[r*3+m] * Rz[m*3+c];
            R[r*3+c] = s;
        }

    float Tc[16]  = {1,0,0,-cog[0], 0,1,0,-cog[1], 0,0,1,-cog[2], 0,0,0,1};
    float Tci[16] = {1,0,0, cog[0], 0,1,0, cog[1], 0,0,1, cog[2], 0,0,0,1};
    float Tt[16]  = {1,0,0,trans[0], 0,1,0,trans[1], 0,0,1,trans[2], 0,0,0,1};
    float Tr[16]  = {R[0],R[1],R[2],0, R[3],R[4],R[5],0, R[6],R[7],R[8],0, 0,0,0,1};

    float tmp1[16], tmp2[16], Trig[16];
    mat4_mul(Tr, Tc, tmp1);
    mat4_mul(Tt, tmp1, tmp2);
    mat4_mul(Tci, tmp2, Trig);

    float flo_inv[16];
    mat4_inv(flo_v2r, flo_inv);

    float tmp3[16], T[16];
    mat4_mul(Trig, ref_v2r, tmp3);
    mat4_mul(flo_inv, tmp3, T);

    for (int r = 0; r < 3; ++r)
        for (int c = 0; c < 4; ++c)
            g_T[r * 4 + c] = T[r * 4 + c];
}

// ---- main resample kernel: one thread per output voxel, T in constant mem ----
__global__ void __launch_bounds__(256)
warp_trilinear_kernel(const float* __restrict__ vol, float* __restrict__ out) {
    const int k = threadIdx.x;          // 0..255
    const int j = blockIdx.y;           // 0..255
    const int i = blockIdx.z;           // 0..255

    const float fi_in = (float)i, fj_in = (float)j, fk_in = (float)k;

    float di = fmaf(c_T[0], fi_in, fmaf(c_T[1], fj_in, fmaf(c_T[2],  fk_in, c_T[3])));
    float dj = fmaf(c_T[4], fi_in, fmaf(c_T[5], fj_in, fmaf(c_T[6],  fk_in, c_T[7])));
    float dk = fmaf(c_T[8], fi_in, fmaf(c_T[9], fj_in, fmaf(c_T[10], fk_in, c_T[11])));

    const float DM1 = (float)(D_DIM - 1), HM1 = (float)(H_DIM - 1), WM1 = (float)(W_DIM - 1);
    const bool ok = (di >= 0.f) & (di <= DM1) & (dj >= 0.f) & (dj <= HM1)
                  & (dk >= 0.f) & (dk <= WM1);

    di = fminf(fmaxf(di, 0.f), DM1);
    dj = fminf(fmaxf(dj, 0.f), HM1);
    dk = fminf(fmaxf(dk, 0.f), WM1);

    const int fi = (int)floorf(di);
    const int fj = (int)floorf(dj);
    const int fk = (int)floorf(dk);
    const int ci = min(fi + 1, D_DIM - 1);
    const int cj = min(fj + 1, H_DIM - 1);
    const int ck = min(fk + 1, W_DIM - 1);

    const float wi = di - (float)fi;
    const float wj = dj - (float)fj;
    const float wk = dk - (float)fk;

    const int base_ff = (fi * H_DIM + fj) * W_DIM;
    const int base_fc = (fi * H_DIM + cj) * W_DIM;
    const int base_cf = (ci * H_DIM + fj) * W_DIM;
    const int base_cc = (ci * H_DIM + cj) * W_DIM;

    const float v000 = __ldg(vol + base_ff + fk);
    const float v001 = __ldg(vol + base_ff + ck);
    const float v010 = __ldg(vol + base_fc + fk);
    const float v011 = __ldg(vol + base_fc + ck);
    const float v100 = __ldg(vol + base_cf + fk);
    const float v101 = __ldg(vol + base_cf + ck);
    const float v110 = __ldg(vol + base_cc + fk);
    const float v111 = __ldg(vol + base_cc + ck);

    const float c00 = fmaf(wk, v001 - v000, v000);
    const float c01 = fmaf(wk, v011 - v010, v010);
    const float c10 = fmaf(wk, v101 - v100, v100);
    const float c11 = fmaf(wk, v111 - v110, v110);
    const float c0  = fmaf(wj, c01 - c00, c00);
    const float c1  = fmaf(wj, c11 - c10, c10);
    float r        = fmaf(wi, c1 - c0, c0);

    r = ok ? r : 0.f;

    out[(i * H_DIM + j) * W_DIM + k] = r;
}

extern "C" void kernel_launch(void* const* d_in, const int* in_sizes, int n_in,
                              void* d_out, int out_size) {
    const float* image   = (const float*)d_in[0];
    const float* angle   = (const float*)d_in[1];
    const float* trans   = (const float*)d_in[2];
    const float* ref_v2r = (const float*)d_in[3];
    const float* flo_v2r = (const float*)d_in[4];
    const float* cog     = (const float*)d_in[5];
    float* out = (float*)d_out;

    compute_T_kernel<<<1, 1>>>(angle, trans, ref_v2r, flo_v2r, cog);

    // Copy the 12 coefficients from the device global into constant memory.
    // Async D2D memcpy: graph-capturable, no allocation.
    void* g_T_addr = nullptr;
    cudaGetSymbolAddress(&g_T_addr, g_T);
    cudaMemcpyToSymbolAsync(c_T, g_T_addr, 12 * sizeof(float), 0,
                            cudaMemcpyDeviceToDevice, 0);

    dim3 block(256, 1, 1);
    dim3 grid(1, H_DIM, D_DIM);
    warp_trilinear_kernel<<<grid, block>>>(image, out);
}